// round 15
// baseline (speedup 1.0000x reference)
#include <cuda_runtime.h>
#include <cuda_fp16.h>
#include <math.h>

#define NN 4
#define C1 128
#define C2 36
#define Hh 192
#define Ww 192
#define HO 190
#define WO 190
#define HW (Hh*Ww)
#define HWO (HO*WO)

typedef unsigned long long ull;

// Scratch (device globals: allocation-free rule)
__device__ float g_bias[C2];             // folded BN bias
__device__ uint4 g_xh[(size_t)NN*16*HW]; // x fp16, 8ch packed [n][cg=16][h][w]
__device__ uint4 g_wfrag[18*12*32];      // deform A frags [s][mt*4+kt][lane]
__device__ uint4 g_ofrag[4*9*2*32];      // offset A frags [(g*9+t)*2+kt][lane]

// ---- packed f32x2 helpers -------------------------------------------------
__device__ __forceinline__ ull fma2(ull a, ull b, ull c) {
    ull d; asm("fma.rn.f32x2 %0,%1,%2,%3;" : "=l"(d) : "l"(a), "l"(b), "l"(c));
    return d;
}
__device__ __forceinline__ ull mul2(ull a, ull b) {
    ull d; asm("mul.rn.f32x2 %0,%1,%2;" : "=l"(d) : "l"(a), "l"(b));
    return d;
}
__device__ __forceinline__ ull pack2(float x, float y) {
    ull d; asm("mov.b64 %0,{%1,%2};" : "=l"(d) : "f"(x), "f"(y));
    return d;
}
__device__ __forceinline__ float lo2(ull a) { return __uint_as_float((unsigned)a); }
__device__ __forceinline__ float hi2(ull a) { return __uint_as_float((unsigned)(a >> 32)); }

__device__ __forceinline__ unsigned h2pack(float a, float b) {
    __half2 h = __floats2half2_rn(a, b);
    return *(unsigned*)&h;
}

// m16n8k16 fp16 MMA, fp32 accumulate
__device__ __forceinline__ void mma16816(float* d, uint4 a,
                                         unsigned b0, unsigned b1) {
    asm volatile(
        "mma.sync.aligned.m16n8k16.row.col.f32.f16.f16.f32 "
        "{%0,%1,%2,%3},{%4,%5,%6,%7},{%8,%9},{%0,%1,%2,%3};"
        : "+f"(d[0]), "+f"(d[1]), "+f"(d[2]), "+f"(d[3])
        : "r"(a.x), "r"(a.y), "r"(a.z), "r"(a.w), "r"(b0), "r"(b1));
}

// ---------------------------------------------------------------------------
// Pack x -> g_xh (fp16, 8ch per uint4) + fused fragment/bias prep.
// First 36 flat blocks additionally build g_wfrag/g_ofrag/g_bias.
// ---------------------------------------------------------------------------
__global__ __launch_bounds__(256) void pack_kernel(
    const float* __restrict__ x,
    const float* __restrict__ dw,
    const float* __restrict__ cwp,
    const float* __restrict__ gamma,
    const float* __restrict__ beta,
    const float* __restrict__ mean,
    const float* __restrict__ var)
{
    // ---- pack
    int idx = blockIdx.x * 256 + threadIdx.x;
    int cg  = blockIdx.y;
    int n   = blockIdx.z;

    const float* xb = x + ((size_t)n * C1 + cg * 8) * HW + idx;
    unsigned w[4];
#pragma unroll
    for (int i = 0; i < 4; i++)
        w[i] = h2pack(xb[(2 * i) * HW], xb[(2 * i + 1) * HW]);
    g_xh[((size_t)n * 16 + cg) * HW + idx] = make_uint4(w[0], w[1], w[2], w[3]);

    // ---- fused prep (first 36 flat blocks)
    int flat = blockIdx.x + 144 * (blockIdx.y + 16 * blockIdx.z);
    if (flat >= 36) return;
    int pidx = flat * 256 + threadIdx.x;

    if (pidx < C2) {
        float s = gamma[pidx] * rsqrtf(var[pidx] + 1e-5f);
        g_bias[pidx] = beta[pidx] - mean[pidx] * s;
    }

    if (pidx < 18 * 12 * 32) {
        int lane = pidx & 31;
        int fi = pidx >> 5;
        int s  = fi / 12;
        int r  = fi % 12;
        int mt = r >> 2, kt = r & 3;
        int t  = s >> 1, dg = s & 1;
        int gq = lane >> 2, tig = lane & 3;

        int o0 = mt * 16 + gq;
        int o1 = o0 + 8;
        int c0 = kt * 16 + 2 * tig;

        auto W = [&](int o, int c) -> float {
            if (o >= C2) return 0.f;
            float sc = gamma[o] * rsqrtf(var[o] + 1e-5f);
            return dw[(o * C1 + dg * 64 + c) * 9 + t] * sc;
        };

        uint4 v;
        v.x = h2pack(W(o0, c0),     W(o0, c0 + 1));
        v.y = h2pack(W(o1, c0),     W(o1, c0 + 1));
        v.z = h2pack(W(o0, c0 + 8), W(o0, c0 + 9));
        v.w = h2pack(W(o1, c0 + 8), W(o1, c0 + 9));
        g_wfrag[pidx] = v;
    }

    int idx2 = pidx - 18 * 12 * 32;
    if (idx2 >= 0 && idx2 < 4 * 9 * 2 * 32) {
        int lane = idx2 & 31;
        int fi = idx2 >> 5;             // (g*9+t)*2 + kt
        int kt = fi & 1;
        int gt = fi >> 1;
        int g = gt / 9, t = gt % 9;
        int gq = lane >> 2, tig = lane & 3;

        int o0 = gq, o1 = gq + 8;
        int c0 = kt * 16 + 2 * tig;

        auto Wv = [&](int o, int c) -> float {
            if (o >= 9) return 0.f;
            return cwp[((g * 9 + o) * 32 + c) * 9 + t];
        };

        uint4 v;
        v.x = h2pack(Wv(o0, c0),     Wv(o0, c0 + 1));
        v.y = h2pack(Wv(o1, c0),     Wv(o1, c0 + 1));
        v.z = h2pack(Wv(o0, c0 + 8), Wv(o0, c0 + 9));
        v.w = h2pack(Wv(o1, c0 + 8), Wv(o1, c0 + 9));
        g_ofrag[fi * 32 + lane] = v;
    }
}

// ---------------------------------------------------------------------------
struct Ctx {
    int o00, o01, o10, o11;
    float W00, W01, W10, W11;
};

__device__ __forceinline__ Ctx make_ctx(int yy, int xx, int i, int j,
                                        float dy, float dx)
{
    Ctx c;
    float py = (float)(yy + i) + dy;
    float px = (float)(xx + j) + dx;
    float fy0 = floorf(py), fx0 = floorf(px);
    float wy1 = py - fy0, wx1 = px - fx0;
    float wy0 = 1.f - wy1, wx0 = 1.f - wx1;

    bool vy0 = (fy0       >= 0.f) && (fy0       <= (float)(Hh - 1));
    bool vy1 = (fy0 + 1.f >= 0.f) && (fy0 + 1.f <= (float)(Hh - 1));
    bool vx0 = (fx0       >= 0.f) && (fx0       <= (float)(Ww - 1));
    bool vx1 = (fx0 + 1.f >= 0.f) && (fx0 + 1.f <= (float)(Ww - 1));

    int y0i = (int)fy0, x0i = (int)fx0;
    int y0c = min(max(y0i,     0), Hh - 1);
    int y1c = min(max(y0i + 1, 0), Hh - 1);
    int x0c = min(max(x0i,     0), Ww - 1);
    int x1c = min(max(x0i + 1, 0), Ww - 1);

    c.W00 = wy0 * wx0 * ((vy0 && vx0) ? 1.f : 0.f);
    c.W01 = wy0 * wx1 * ((vy0 && vx1) ? 1.f : 0.f);
    c.W10 = wy1 * wx0 * ((vy1 && vx0) ? 1.f : 0.f);
    c.W11 = wy1 * wx1 * ((vy1 && vx1) ? 1.f : 0.f);

    c.o00 = y0c * Ww + x0c; c.o01 = y0c * Ww + x1c;
    c.o10 = y1c * Ww + x0c; c.o11 = y1c * Ww + x1c;
    return c;
}

// ---------------------------------------------------------------------------
// FUSED offset-conv + deformable conv + BN + Mish via tensor cores.
// Phase 1: block computes its own 128 pixels' 36 offsets (grouped conv MMA,
//          k=32 per group, 9 taps) into smem offs[36][128].
// Phase 2: 18-stage deform MMA (unchanged), offsets read from smem.
// All data flow is warp-private -> __syncwarp only.
// ---------------------------------------------------------------------------
__global__ __launch_bounds__(128, 4) void deform_kernel(float* __restrict__ out)
{
    __shared__ __align__(16) char  vsm[128 * 144];   // B tiles (both phases)
    __shared__ float offs[36 * 128];                  // offsets [o][px] 18KB

    int tid  = threadIdx.x;
    int warp = tid >> 5, lane = tid & 31;
    int gq = lane >> 2, tig = lane & 3;
    int n = blockIdx.y;
    int blockbase = blockIdx.x * 128;

    int ps = min(blockbase + tid, HWO - 1);
    int ys = ps / WO, xs = ps % WO;

    const uint4* xh = g_xh + (size_t)n * 16 * HW;
    char* myrow = vsm + (size_t)tid * 144;

    // ======== Phase 1: offset conv ========
    for (int gr = 0; gr < 4; gr++) {
        const uint4* xg = xh + (size_t)(gr * 4) * HW;
        float oacc[4][4];
#pragma unroll
        for (int nt = 0; nt < 4; nt++)
#pragma unroll
            for (int i = 0; i < 4; i++) oacc[nt][i] = 0.f;

        for (int t = 0; t < 9; t++) {
            int ti = t / 3, tj = t % 3;
            int pos = (ys + ti) * Ww + (xs + tj);
#pragma unroll
            for (int cg = 0; cg < 4; cg++) {
                uint4 q = __ldg(xg + (size_t)cg * HW + pos);
                *(uint4*)(myrow + cg * 16) = q;
            }
            __syncwarp();

            uint4 af0 = __ldg(&g_ofrag[(((gr * 9 + t) * 2) + 0) * 32 + lane]);
            uint4 af1 = __ldg(&g_ofrag[(((gr * 9 + t) * 2) + 1) * 32 + lane]);
#pragma unroll
            for (int nt = 0; nt < 4; nt++) {
                const char* rb = vsm + (size_t)(warp * 32 + nt * 8 + gq) * 144
                               + tig * 4;
                unsigned b0 = *(const unsigned*)(rb);
                unsigned b1 = *(const unsigned*)(rb + 16);
                unsigned b2 = *(const unsigned*)(rb + 32);
                unsigned b3 = *(const unsigned*)(rb + 48);
                mma16816(oacc[nt], af0, b0, b1);
                mma16816(oacc[nt], af1, b2, b3);
            }
            __syncwarp();
        }

        // write offsets to smem: rows o = gr*9+gq, plus o = gr*9+8 (gq==0)
#pragma unroll
        for (int nt = 0; nt < 4; nt++) {
            int pxl = warp * 32 + nt * 8 + 2 * tig;
            offs[(gr * 9 + gq) * 128 + pxl]     = oacc[nt][0];
            offs[(gr * 9 + gq) * 128 + pxl + 1] = oacc[nt][1];
            if (gq == 0) {
                offs[(gr * 9 + 8) * 128 + pxl]     = oacc[nt][2];
                offs[(gr * 9 + 8) * 128 + pxl + 1] = oacc[nt][3];
            }
        }
        __syncwarp();
    }

    // ======== Phase 2: deformable conv ========
    float acc[3][4][4];
#pragma unroll
    for (int mt = 0; mt < 3; mt++)
#pragma unroll
        for (int nt = 0; nt < 4; nt++)
#pragma unroll
            for (int i = 0; i < 4; i++) acc[mt][nt][i] = 0.f;

    for (int s = 0; s < 18; s++) {
        int t = s >> 1, dg = s & 1;
        int ti = t / 3, tj = t % 3;

        float dy = offs[(dg * 18 + t * 2    ) * 128 + tid];
        float dx = offs[(dg * 18 + t * 2 + 1) * 128 + tid];
        Ctx C = make_ctx(ys, xs, ti, tj, dy, dx);
        ull W00p = pack2(C.W00, C.W00), W01p = pack2(C.W01, C.W01);
        ull W10p = pack2(C.W10, C.W10), W11p = pack2(C.W11, C.W11);

#pragma unroll 4
        for (int cg = 0; cg < 8; cg++) {
            const uint4* pc = xh + (size_t)(dg * 8 + cg) * HW;
            uint4 q00 = __ldg(pc + C.o00);
            uint4 q01 = __ldg(pc + C.o01);
            uint4 q10 = __ldg(pc + C.o10);
            uint4 q11 = __ldg(pc + C.o11);
            const unsigned* u00 = (const unsigned*)&q00;
            const unsigned* u01 = (const unsigned*)&q01;
            const unsigned* u10 = (const unsigned*)&q10;
            const unsigned* u11 = (const unsigned*)&q11;
            uint4 hv;
            unsigned* hp = (unsigned*)&hv;
#pragma unroll
            for (int i = 0; i < 4; i++) {
                float2 f00 = __half22float2(*(const __half2*)&u00[i]);
                float2 f01 = __half22float2(*(const __half2*)&u01[i]);
                float2 f10 = __half22float2(*(const __half2*)&u10[i]);
                float2 f11 = __half22float2(*(const __half2*)&u11[i]);
                ull v = fma2(W00p, pack2(f00.x, f00.y),
                        fma2(W01p, pack2(f01.x, f01.y),
                        fma2(W10p, pack2(f10.x, f10.y),
                        mul2(W11p, pack2(f11.x, f11.y)))));
                hp[i] = h2pack(lo2(v), hi2(v));
            }
            *(uint4*)(myrow + cg * 16) = hv;
        }
        __syncwarp();

        uint4 af[12];
#pragma unroll
        for (int f = 0; f < 12; f++)
            af[f] = __ldg(&g_wfrag[(s * 12 + f) * 32 + lane]);

#pragma unroll
        for (int nt = 0; nt < 4; nt++) {
            const char* rb = vsm + (size_t)(warp * 32 + nt * 8 + gq) * 144
                           + tig * 4;
            unsigned b[8];
#pragma unroll
            for (int kt = 0; kt < 4; kt++) {
                b[2 * kt]     = *(const unsigned*)(rb + kt * 32);
                b[2 * kt + 1] = *(const unsigned*)(rb + kt * 32 + 16);
            }
#pragma unroll
            for (int mt = 0; mt < 3; mt++)
#pragma unroll
                for (int kt = 0; kt < 4; kt++)
                    mma16816(acc[mt][nt], af[mt * 4 + kt],
                             b[2 * kt], b[2 * kt + 1]);
        }
        __syncwarp();
    }

    // ---- epilogue: bias + Mish
    float* ob = out + (size_t)n * C2 * HWO;
#pragma unroll
    for (int mt = 0; mt < 3; mt++) {
        int o0 = mt * 16 + gq;
        int o1 = o0 + 8;
#pragma unroll
        for (int nt = 0; nt < 4; nt++) {
            int px = blockbase + warp * 32 + nt * 8 + 2 * tig;
            const float* a = acc[mt][nt];
#pragma unroll
            for (int h = 0; h < 2; h++) {
                int o = h ? o1 : o0;
                if (o < C2) {
                    float b = __ldg(g_bias + o);
#pragma unroll
                    for (int e = 0; e < 2; e++) {
                        int p = px + e;
                        if (p < HWO) {
                            float z = a[h * 2 + e] + b;
                            float sp = (z > 20.f) ? z : log1pf(expf(z));
                            ob[(size_t)o * HWO + p] = z * tanhf(sp);
                        }
                    }
                }
            }
        }
    }
}

// ---------------------------------------------------------------------------
extern "C" void kernel_launch(void* const* d_in, const int* in_sizes, int n_in,
                              void* d_out, int out_size)
{
    const float* x        = (const float*)d_in[0];
    const float* conv_w   = (const float*)d_in[1];
    const float* deform_w = (const float*)d_in[2];
    const float* bn_gamma = (const float*)d_in[3];
    const float* bn_beta  = (const float*)d_in[4];
    const float* bn_mean  = (const float*)d_in[5];
    const float* bn_var   = (const float*)d_in[6];
    float* out = (float*)d_out;

    static bool attr_set = false;
    if (!attr_set) {
        cudaFuncSetAttribute(deform_kernel,
                             cudaFuncAttributePreferredSharedMemoryCarveout,
                             100);
        attr_set = true;
    }

    pack_kernel<<<dim3(HW / 256, 16, NN), 256>>>(
        x, deform_w, conv_w, bn_gamma, bn_beta, bn_mean, bn_var);

    deform_kernel<<<dim3((HWO + 127) / 128, NN), 128>>>(out);
}

// round 16
// speedup vs baseline: 1.0694x; 1.0694x over previous
#include <cuda_runtime.h>
#include <cuda_fp16.h>
#include <math.h>

#define NN 4
#define C1 128
#define C2 36
#define Hh 192
#define Ww 192
#define HO 190
#define WO 190
#define HW (Hh*Ww)
#define HWO (HO*WO)

typedef unsigned long long ull;

// Scratch (device globals: allocation-free rule)
__device__ float g_offset[NN*C2*HWO];    // offset conv output [N,36,HO,WO]
__device__ float g_bias[C2];             // folded BN bias
__device__ uint4 g_xh[(size_t)NN*16*HW]; // x fp16, 8ch packed [n][cg=16][h][w]
__device__ uint4 g_wfrag[18*12*32];      // deform A frags [s][mt*4+kt][lane]
__device__ uint4 g_ofrag[4*9*2*32];      // offset A frags [(g*9+t)*2+kt][lane]

// ---- packed f32x2 helpers -------------------------------------------------
__device__ __forceinline__ ull fma2(ull a, ull b, ull c) {
    ull d; asm("fma.rn.f32x2 %0,%1,%2,%3;" : "=l"(d) : "l"(a), "l"(b), "l"(c));
    return d;
}
__device__ __forceinline__ ull mul2(ull a, ull b) {
    ull d; asm("mul.rn.f32x2 %0,%1,%2;" : "=l"(d) : "l"(a), "l"(b));
    return d;
}
__device__ __forceinline__ ull pack2(float x, float y) {
    ull d; asm("mov.b64 %0,{%1,%2};" : "=l"(d) : "f"(x), "f"(y));
    return d;
}
__device__ __forceinline__ float lo2(ull a) { return __uint_as_float((unsigned)a); }
__device__ __forceinline__ float hi2(ull a) { return __uint_as_float((unsigned)(a >> 32)); }

__device__ __forceinline__ unsigned h2pack(float a, float b) {
    __half2 h = __floats2half2_rn(a, b);
    return *(unsigned*)&h;
}

// m16n8k16 fp16 MMA, fp32 accumulate
__device__ __forceinline__ void mma16816(float* d, uint4 a,
                                         unsigned b0, unsigned b1) {
    asm volatile(
        "mma.sync.aligned.m16n8k16.row.col.f32.f16.f16.f32 "
        "{%0,%1,%2,%3},{%4,%5,%6,%7},{%8,%9},{%0,%1,%2,%3};"
        : "+f"(d[0]), "+f"(d[1]), "+f"(d[2]), "+f"(d[3])
        : "r"(a.x), "r"(a.y), "r"(a.z), "r"(a.w), "r"(b0), "r"(b1));
}

// ---------------------------------------------------------------------------
// Pack x -> g_xh (fp16, 8ch per uint4) + fused fragment/bias prep.
// First 36 flat blocks additionally build g_wfrag/g_ofrag/g_bias.
// ---------------------------------------------------------------------------
__global__ __launch_bounds__(256) void pack_kernel(
    const float* __restrict__ x,
    const float* __restrict__ dw,
    const float* __restrict__ cwp,
    const float* __restrict__ gamma,
    const float* __restrict__ beta,
    const float* __restrict__ mean,
    const float* __restrict__ var)
{
    // ---- pack
    int idx = blockIdx.x * 256 + threadIdx.x;
    int cg  = blockIdx.y;
    int n   = blockIdx.z;

    const float* xb = x + ((size_t)n * C1 + cg * 8) * HW + idx;
    unsigned w[4];
#pragma unroll
    for (int i = 0; i < 4; i++)
        w[i] = h2pack(xb[(2 * i) * HW], xb[(2 * i + 1) * HW]);
    g_xh[((size_t)n * 16 + cg) * HW + idx] = make_uint4(w[0], w[1], w[2], w[3]);

    // ---- fused prep (first 36 flat blocks)
    int flat = blockIdx.x + 144 * (blockIdx.y + 16 * blockIdx.z);
    if (flat >= 36) return;
    int pidx = flat * 256 + threadIdx.x;

    if (pidx < C2) {
        float s = gamma[pidx] * rsqrtf(var[pidx] + 1e-5f);
        g_bias[pidx] = beta[pidx] - mean[pidx] * s;
    }

    if (pidx < 18 * 12 * 32) {
        int lane = pidx & 31;
        int fi = pidx >> 5;
        int s  = fi / 12;
        int r  = fi % 12;
        int mt = r >> 2, kt = r & 3;
        int t  = s >> 1, dg = s & 1;
        int gq = lane >> 2, tig = lane & 3;

        int o0 = mt * 16 + gq;
        int o1 = o0 + 8;
        int c0 = kt * 16 + 2 * tig;

        auto W = [&](int o, int c) -> float {
            if (o >= C2) return 0.f;
            float sc = gamma[o] * rsqrtf(var[o] + 1e-5f);
            return dw[(o * C1 + dg * 64 + c) * 9 + t] * sc;
        };

        uint4 v;
        v.x = h2pack(W(o0, c0),     W(o0, c0 + 1));
        v.y = h2pack(W(o1, c0),     W(o1, c0 + 1));
        v.z = h2pack(W(o0, c0 + 8), W(o0, c0 + 9));
        v.w = h2pack(W(o1, c0 + 8), W(o1, c0 + 9));
        g_wfrag[pidx] = v;
    }

    int idx2 = pidx - 18 * 12 * 32;
    if (idx2 >= 0 && idx2 < 4 * 9 * 2 * 32) {
        int lane = idx2 & 31;
        int fi = idx2 >> 5;             // (g*9+t)*2 + kt
        int kt = fi & 1;
        int gt = fi >> 1;
        int g = gt / 9, t = gt % 9;
        int gq = lane >> 2, tig = lane & 3;

        int o0 = gq, o1 = gq + 8;
        int c0 = kt * 16 + 2 * tig;

        auto Wv = [&](int o, int c) -> float {
            if (o >= 9) return 0.f;
            return cwp[((g * 9 + o) * 32 + c) * 9 + t];
        };

        uint4 v;
        v.x = h2pack(Wv(o0, c0),     Wv(o0, c0 + 1));
        v.y = h2pack(Wv(o1, c0),     Wv(o1, c0 + 1));
        v.z = h2pack(Wv(o0, c0 + 8), Wv(o0, c0 + 9));
        v.w = h2pack(Wv(o1, c0 + 8), Wv(o1, c0 + 9));
        g_ofrag[fi * 32 + lane] = v;
    }
}

// ---------------------------------------------------------------------------
// Offset-generating grouped conv via tensor cores (R13 proven version).
// ---------------------------------------------------------------------------
__global__ __launch_bounds__(128, 4) void offset_mma_kernel()
{
    __shared__ __align__(16) char vsm[128 * 80];   // [px][32 ch fp16 + pad]

    int tid  = threadIdx.x;
    int warp = tid >> 5, lane = tid & 31;
    int gq = lane >> 2, tig = lane & 3;
    int n = blockIdx.y >> 2;
    int g = blockIdx.y & 3;
    int blockbase = blockIdx.x * 128;

    int ps = min(blockbase + tid, HWO - 1);
    int ys = ps / WO, xs = ps % WO;

    const uint4* xh = g_xh + ((size_t)n * 16 + g * 4) * HW;

    float acc[4][4];
#pragma unroll
    for (int nt = 0; nt < 4; nt++)
#pragma unroll
        for (int i = 0; i < 4; i++) acc[nt][i] = 0.f;

    char* myrow = vsm + (size_t)tid * 80;

    for (int t = 0; t < 9; t++) {
        int ti = t / 3, tj = t % 3;
        int pos = (ys + ti) * Ww + (xs + tj);

#pragma unroll
        for (int cg = 0; cg < 4; cg++) {
            uint4 q = __ldg(xh + (size_t)cg * HW + pos);
            *(uint4*)(myrow + cg * 16) = q;
        }
        __syncwarp();

        uint4 af0 = __ldg(&g_ofrag[(((g * 9 + t) * 2) + 0) * 32 + lane]);
        uint4 af1 = __ldg(&g_ofrag[(((g * 9 + t) * 2) + 1) * 32 + lane]);

#pragma unroll
        for (int nt = 0; nt < 4; nt++) {
            const char* rb = vsm + (size_t)(warp * 32 + nt * 8 + gq) * 80
                           + tig * 4;
            unsigned b0 = *(const unsigned*)(rb);
            unsigned b1 = *(const unsigned*)(rb + 16);
            unsigned b2 = *(const unsigned*)(rb + 32);
            unsigned b3 = *(const unsigned*)(rb + 48);
            mma16816(acc[nt], af0, b0, b1);
            mma16816(acc[nt], af1, b2, b3);
        }
        __syncwarp();
    }

    float* op = g_offset + ((size_t)n * C2 + g * 9) * HWO;
#pragma unroll
    for (int nt = 0; nt < 4; nt++) {
        int px = blockbase + warp * 32 + nt * 8 + 2 * tig;
#pragma unroll
        for (int e = 0; e < 2; e++) {
            int p = px + e;
            if (p < HWO) {
                op[(size_t)gq * HWO + p] = acc[nt][e];
                if (gq == 0)
                    op[(size_t)8 * HWO + p] = acc[nt][2 + e];
            }
        }
    }
}

// ---------------------------------------------------------------------------
struct Ctx {
    int o00, o01, o10, o11;
    float W00, W01, W10, W11;
};

__device__ __forceinline__ Ctx make_ctx(int yy, int xx, int i, int j,
                                        float dy, float dx)
{
    Ctx c;
    float py = (float)(yy + i) + dy;
    float px = (float)(xx + j) + dx;
    float fy0 = floorf(py), fx0 = floorf(px);
    float wy1 = py - fy0, wx1 = px - fx0;
    float wy0 = 1.f - wy1, wx0 = 1.f - wx1;

    bool vy0 = (fy0       >= 0.f) && (fy0       <= (float)(Hh - 1));
    bool vy1 = (fy0 + 1.f >= 0.f) && (fy0 + 1.f <= (float)(Hh - 1));
    bool vx0 = (fx0       >= 0.f) && (fx0       <= (float)(Ww - 1));
    bool vx1 = (fx0 + 1.f >= 0.f) && (fx0 + 1.f <= (float)(Ww - 1));

    int y0i = (int)fy0, x0i = (int)fx0;
    int y0c = min(max(y0i,     0), Hh - 1);
    int y1c = min(max(y0i + 1, 0), Hh - 1);
    int x0c = min(max(x0i,     0), Ww - 1);
    int x1c = min(max(x0i + 1, 0), Ww - 1);

    c.W00 = wy0 * wx0 * ((vy0 && vx0) ? 1.f : 0.f);
    c.W01 = wy0 * wx1 * ((vy0 && vx1) ? 1.f : 0.f);
    c.W10 = wy1 * wx0 * ((vy1 && vx0) ? 1.f : 0.f);
    c.W11 = wy1 * wx1 * ((vy1 && vx1) ? 1.f : 0.f);

    c.o00 = y0c * Ww + x0c; c.o01 = y0c * Ww + x1c;
    c.o10 = y1c * Ww + x0c; c.o11 = y1c * Ww + x1c;
    return c;
}

// ---------------------------------------------------------------------------
// Deformable conv + folded BN + Mish via tensor cores (R14 proven version).
// ---------------------------------------------------------------------------
__global__ __launch_bounds__(128, 4) void deform_kernel(float* __restrict__ out)
{
    __shared__ __align__(16) char vsm[128 * 144];   // V fp16 [128px][72 halves]

    int tid  = threadIdx.x;
    int warp = tid >> 5, lane = tid & 31;
    int g = lane >> 2, tig = lane & 3;
    int n = blockIdx.y;
    int blockbase = blockIdx.x * 128;

    int ps = min(blockbase + tid, HWO - 1);
    int ys = ps / WO, xs = ps % WO;

    const uint4* xh  = g_xh + (size_t)n * 16 * HW;
    const float* off = g_offset + (size_t)n * C2 * HWO + ps;

    float acc[3][4][4];
#pragma unroll
    for (int mt = 0; mt < 3; mt++)
#pragma unroll
        for (int nt = 0; nt < 4; nt++)
#pragma unroll
            for (int i = 0; i < 4; i++) acc[mt][nt][i] = 0.f;

    char* myrow = vsm + (size_t)tid * 144;

    for (int s = 0; s < 18; s++) {
        int t = s >> 1, dg = s & 1;
        int ti = t / 3, tj = t % 3;

        float dy = off[(dg * 18 + t * 2    ) * HWO];
        float dx = off[(dg * 18 + t * 2 + 1) * HWO];
        Ctx C = make_ctx(ys, xs, ti, tj, dy, dx);
        ull W00p = pack2(C.W00, C.W00), W01p = pack2(C.W01, C.W01);
        ull W10p = pack2(C.W10, C.W10), W11p = pack2(C.W11, C.W11);

#pragma unroll 4
        for (int cg = 0; cg < 8; cg++) {
            const uint4* pc = xh + (size_t)(dg * 8 + cg) * HW;
            uint4 q00 = __ldg(pc + C.o00);
            uint4 q01 = __ldg(pc + C.o01);
            uint4 q10 = __ldg(pc + C.o10);
            uint4 q11 = __ldg(pc + C.o11);
            const unsigned* u00 = (const unsigned*)&q00;
            const unsigned* u01 = (const unsigned*)&q01;
            const unsigned* u10 = (const unsigned*)&q10;
            const unsigned* u11 = (const unsigned*)&q11;
            uint4 hv;
            unsigned* hp = (unsigned*)&hv;
#pragma unroll
            for (int i = 0; i < 4; i++) {
                float2 f00 = __half22float2(*(const __half2*)&u00[i]);
                float2 f01 = __half22float2(*(const __half2*)&u01[i]);
                float2 f10 = __half22float2(*(const __half2*)&u10[i]);
                float2 f11 = __half22float2(*(const __half2*)&u11[i]);
                ull v = fma2(W00p, pack2(f00.x, f00.y),
                        fma2(W01p, pack2(f01.x, f01.y),
                        fma2(W10p, pack2(f10.x, f10.y),
                        mul2(W11p, pack2(f11.x, f11.y)))));
                hp[i] = h2pack(lo2(v), hi2(v));
            }
            *(uint4*)(myrow + cg * 16) = hv;
        }
        __syncwarp();

        uint4 af[12];
#pragma unroll
        for (int f = 0; f < 12; f++)
            af[f] = __ldg(&g_wfrag[(s * 12 + f) * 32 + lane]);

#pragma unroll
        for (int nt = 0; nt < 4; nt++) {
            const char* rb = vsm + (size_t)(warp * 32 + nt * 8 + g) * 144
                           + tig * 4;
            unsigned b[8];
#pragma unroll
            for (int kt = 0; kt < 4; kt++) {
                b[2 * kt]     = *(const unsigned*)(rb + kt * 32);
                b[2 * kt + 1] = *(const unsigned*)(rb + kt * 32 + 16);
            }
#pragma unroll
            for (int mt = 0; mt < 3; mt++)
#pragma unroll
                for (int kt = 0; kt < 4; kt++)
                    mma16816(acc[mt][nt], af[mt * 4 + kt],
                             b[2 * kt], b[2 * kt + 1]);
        }
        __syncwarp();
    }

    // ---- epilogue: bias + Mish
    float* ob = out + (size_t)n * C2 * HWO;
#pragma unroll
    for (int mt = 0; mt < 3; mt++) {
        int o0 = mt * 16 + g;
        int o1 = o0 + 8;
#pragma unroll
        for (int nt = 0; nt < 4; nt++) {
            int px = blockbase + warp * 32 + nt * 8 + 2 * tig;
            const float* a = acc[mt][nt];
#pragma unroll
            for (int h = 0; h < 2; h++) {
                int o = h ? o1 : o0;
                if (o < C2) {
                    float b = __ldg(g_bias + o);
#pragma unroll
                    for (int e = 0; e < 2; e++) {
                        int p = px + e;
                        if (p < HWO) {
                            float z = a[h * 2 + e] + b;
                            float sp = (z > 20.f) ? z : log1pf(expf(z));
                            ob[(size_t)o * HWO + p] = z * tanhf(sp);
                        }
                    }
                }
            }
        }
    }
}

// ---------------------------------------------------------------------------
extern "C" void kernel_launch(void* const* d_in, const int* in_sizes, int n_in,
                              void* d_out, int out_size)
{
    const float* x        = (const float*)d_in[0];
    const float* conv_w   = (const float*)d_in[1];
    const float* deform_w = (const float*)d_in[2];
    const float* bn_gamma = (const float*)d_in[3];
    const float* bn_beta  = (const float*)d_in[4];
    const float* bn_mean  = (const float*)d_in[5];
    const float* bn_var   = (const float*)d_in[6];
    float* out = (float*)d_out;

    pack_kernel<<<dim3(HW / 256, 16, NN), 256>>>(
        x, deform_w, conv_w, bn_gamma, bn_beta, bn_mean, bn_var);

    offset_mma_kernel<<<dim3((HWO + 127) / 128, NN * 4), 128>>>();

    deform_kernel<<<dim3((HWO + 127) / 128, NN), 128>>>(out);
}

// round 17
// speedup vs baseline: 1.0847x; 1.0143x over previous
#include <cuda_runtime.h>
#include <cuda_fp16.h>
#include <math.h>

#define NN 4
#define C1 128
#define C2 36
#define Hh 192
#define Ww 192
#define HO 190
#define WO 190
#define HW (Hh*Ww)
#define HWO (HO*WO)

typedef unsigned long long ull;

// Scratch (device globals: allocation-free rule)
__device__ float g_offset[NN*C2*HWO];    // offset conv output [N,36,HO,WO]
__device__ float g_bias[C2];             // folded BN bias
__device__ uint4 g_xh[(size_t)NN*16*HW]; // x fp16, 8ch packed [n][cg=16][h][w]
__device__ uint4 g_wfrag[18*12*32];      // deform A frags [s][mt*4+kt][lane]
__device__ uint4 g_ofrag[4*9*2*32];      // offset A frags [(g*9+t)*2+kt][lane]

// ---- packed f32x2 helpers -------------------------------------------------
__device__ __forceinline__ ull fma2(ull a, ull b, ull c) {
    ull d; asm("fma.rn.f32x2 %0,%1,%2,%3;" : "=l"(d) : "l"(a), "l"(b), "l"(c));
    return d;
}
__device__ __forceinline__ ull mul2(ull a, ull b) {
    ull d; asm("mul.rn.f32x2 %0,%1,%2;" : "=l"(d) : "l"(a), "l"(b));
    return d;
}
__device__ __forceinline__ ull pack2(float x, float y) {
    ull d; asm("mov.b64 %0,{%1,%2};" : "=l"(d) : "f"(x), "f"(y));
    return d;
}
__device__ __forceinline__ float lo2(ull a) { return __uint_as_float((unsigned)a); }
__device__ __forceinline__ float hi2(ull a) { return __uint_as_float((unsigned)(a >> 32)); }

__device__ __forceinline__ unsigned h2pack(float a, float b) {
    __half2 h = __floats2half2_rn(a, b);
    return *(unsigned*)&h;
}

// m16n8k16 fp16 MMA, fp32 accumulate
__device__ __forceinline__ void mma16816(float* d, uint4 a,
                                         unsigned b0, unsigned b1) {
    asm volatile(
        "mma.sync.aligned.m16n8k16.row.col.f32.f16.f16.f32 "
        "{%0,%1,%2,%3},{%4,%5,%6,%7},{%8,%9},{%0,%1,%2,%3};"
        : "+f"(d[0]), "+f"(d[1]), "+f"(d[2]), "+f"(d[3])
        : "r"(a.x), "r"(a.y), "r"(a.z), "r"(a.w), "r"(b0), "r"(b1));
}

// ---------------------------------------------------------------------------
// Pack x -> g_xh (fp16, 8ch per uint4) + fused fragment/bias prep.
// First 36 flat blocks additionally build g_wfrag/g_ofrag/g_bias.
// ---------------------------------------------------------------------------
__global__ __launch_bounds__(256) void pack_kernel(
    const float* __restrict__ x,
    const float* __restrict__ dw,
    const float* __restrict__ cwp,
    const float* __restrict__ gamma,
    const float* __restrict__ beta,
    const float* __restrict__ mean,
    const float* __restrict__ var)
{
    // ---- pack
    int idx = blockIdx.x * 256 + threadIdx.x;
    int cg  = blockIdx.y;
    int n   = blockIdx.z;

    const float* xb = x + ((size_t)n * C1 + cg * 8) * HW + idx;
    unsigned w[4];
#pragma unroll
    for (int i = 0; i < 4; i++)
        w[i] = h2pack(xb[(2 * i) * HW], xb[(2 * i + 1) * HW]);
    g_xh[((size_t)n * 16 + cg) * HW + idx] = make_uint4(w[0], w[1], w[2], w[3]);

    // ---- fused prep (first 36 flat blocks)
    int flat = blockIdx.x + 144 * (blockIdx.y + 16 * blockIdx.z);
    if (flat >= 36) return;
    int pidx = flat * 256 + threadIdx.x;

    if (pidx < C2) {
        float s = gamma[pidx] * rsqrtf(var[pidx] + 1e-5f);
        g_bias[pidx] = beta[pidx] - mean[pidx] * s;
    }

    if (pidx < 18 * 12 * 32) {
        int lane = pidx & 31;
        int fi = pidx >> 5;
        int s  = fi / 12;
        int r  = fi % 12;
        int mt = r >> 2, kt = r & 3;
        int t  = s >> 1, dg = s & 1;
        int gq = lane >> 2, tig = lane & 3;

        int o0 = mt * 16 + gq;
        int o1 = o0 + 8;
        int c0 = kt * 16 + 2 * tig;

        auto W = [&](int o, int c) -> float {
            if (o >= C2) return 0.f;
            float sc = gamma[o] * rsqrtf(var[o] + 1e-5f);
            return dw[(o * C1 + dg * 64 + c) * 9 + t] * sc;
        };

        uint4 v;
        v.x = h2pack(W(o0, c0),     W(o0, c0 + 1));
        v.y = h2pack(W(o1, c0),     W(o1, c0 + 1));
        v.z = h2pack(W(o0, c0 + 8), W(o0, c0 + 9));
        v.w = h2pack(W(o1, c0 + 8), W(o1, c0 + 9));
        g_wfrag[pidx] = v;
    }

    int idx2 = pidx - 18 * 12 * 32;
    if (idx2 >= 0 && idx2 < 4 * 9 * 2 * 32) {
        int lane = idx2 & 31;
        int fi = idx2 >> 5;             // (g*9+t)*2 + kt
        int kt = fi & 1;
        int gt = fi >> 1;
        int g = gt / 9, t = gt % 9;
        int gq = lane >> 2, tig = lane & 3;

        int o0 = gq, o1 = gq + 8;
        int c0 = kt * 16 + 2 * tig;

        auto Wv = [&](int o, int c) -> float {
            if (o >= 9) return 0.f;
            return cwp[((g * 9 + o) * 32 + c) * 9 + t];
        };

        uint4 v;
        v.x = h2pack(Wv(o0, c0),     Wv(o0, c0 + 1));
        v.y = h2pack(Wv(o1, c0),     Wv(o1, c0 + 1));
        v.z = h2pack(Wv(o0, c0 + 8), Wv(o0, c0 + 9));
        v.w = h2pack(Wv(o1, c0 + 8), Wv(o1, c0 + 9));
        g_ofrag[fi * 32 + lane] = v;
    }
}

// ---------------------------------------------------------------------------
// Offset-generating grouped conv via tensor cores (float2 epilogue).
// ---------------------------------------------------------------------------
__global__ __launch_bounds__(128, 4) void offset_mma_kernel()
{
    __shared__ __align__(16) char vsm[128 * 80];   // [px][32 ch fp16 + pad]

    int tid  = threadIdx.x;
    int warp = tid >> 5, lane = tid & 31;
    int gq = lane >> 2, tig = lane & 3;
    int n = blockIdx.y >> 2;
    int g = blockIdx.y & 3;
    int blockbase = blockIdx.x * 128;

    int ps = min(blockbase + tid, HWO - 1);
    int ys = ps / WO, xs = ps % WO;

    const uint4* xh = g_xh + ((size_t)n * 16 + g * 4) * HW;

    float acc[4][4];
#pragma unroll
    for (int nt = 0; nt < 4; nt++)
#pragma unroll
        for (int i = 0; i < 4; i++) acc[nt][i] = 0.f;

    char* myrow = vsm + (size_t)tid * 80;

    for (int t = 0; t < 9; t++) {
        int ti = t / 3, tj = t % 3;
        int pos = (ys + ti) * Ww + (xs + tj);

#pragma unroll
        for (int cg = 0; cg < 4; cg++) {
            uint4 q = __ldg(xh + (size_t)cg * HW + pos);
            *(uint4*)(myrow + cg * 16) = q;
        }
        __syncwarp();

        uint4 af0 = __ldg(&g_ofrag[(((g * 9 + t) * 2) + 0) * 32 + lane]);
        uint4 af1 = __ldg(&g_ofrag[(((g * 9 + t) * 2) + 1) * 32 + lane]);

#pragma unroll
        for (int nt = 0; nt < 4; nt++) {
            const char* rb = vsm + (size_t)(warp * 32 + nt * 8 + gq) * 80
                           + tig * 4;
            unsigned b0 = *(const unsigned*)(rb);
            unsigned b1 = *(const unsigned*)(rb + 16);
            unsigned b2 = *(const unsigned*)(rb + 32);
            unsigned b3 = *(const unsigned*)(rb + 48);
            mma16816(acc[nt], af0, b0, b1);
            mma16816(acc[nt], af1, b2, b3);
        }
        __syncwarp();
    }

    // epilogue: float2 stores (p even, HWO even => p < HWO implies p+1 < HWO)
    float* op = g_offset + ((size_t)n * C2 + g * 9) * HWO;
#pragma unroll
    for (int nt = 0; nt < 4; nt++) {
        int p = blockbase + warp * 32 + nt * 8 + 2 * tig;
        if (p < HWO) {
            *(float2*)(op + (size_t)gq * HWO + p) =
                make_float2(acc[nt][0], acc[nt][1]);
            if (gq == 0)
                *(float2*)(op + (size_t)8 * HWO + p) =
                    make_float2(acc[nt][2], acc[nt][3]);
        }
    }
}

// ---------------------------------------------------------------------------
struct Ctx {
    int o00, o01, o10, o11;
    float W00, W01, W10, W11;
};

__device__ __forceinline__ Ctx make_ctx(int yy, int xx, int i, int j,
                                        float dy, float dx)
{
    Ctx c;
    float py = (float)(yy + i) + dy;
    float px = (float)(xx + j) + dx;
    float fy0 = floorf(py), fx0 = floorf(px);
    float wy1 = py - fy0, wx1 = px - fx0;
    float wy0 = 1.f - wy1, wx0 = 1.f - wx1;

    bool vy0 = (fy0       >= 0.f) && (fy0       <= (float)(Hh - 1));
    bool vy1 = (fy0 + 1.f >= 0.f) && (fy0 + 1.f <= (float)(Hh - 1));
    bool vx0 = (fx0       >= 0.f) && (fx0       <= (float)(Ww - 1));
    bool vx1 = (fx0 + 1.f >= 0.f) && (fx0 + 1.f <= (float)(Ww - 1));

    int y0i = (int)fy0, x0i = (int)fx0;
    int y0c = min(max(y0i,     0), Hh - 1);
    int y1c = min(max(y0i + 1, 0), Hh - 1);
    int x0c = min(max(x0i,     0), Ww - 1);
    int x1c = min(max(x0i + 1, 0), Ww - 1);

    c.W00 = wy0 * wx0 * ((vy0 && vx0) ? 1.f : 0.f);
    c.W01 = wy0 * wx1 * ((vy0 && vx1) ? 1.f : 0.f);
    c.W10 = wy1 * wx0 * ((vy1 && vx0) ? 1.f : 0.f);
    c.W11 = wy1 * wx1 * ((vy1 && vx1) ? 1.f : 0.f);

    c.o00 = y0c * Ww + x0c; c.o01 = y0c * Ww + x1c;
    c.o10 = y1c * Ww + x0c; c.o11 = y1c * Ww + x1c;
    return c;
}

// ---------------------------------------------------------------------------
// Deformable conv + folded BN + Mish via tensor cores (float2 epilogue).
// ---------------------------------------------------------------------------
__global__ __launch_bounds__(128, 4) void deform_kernel(float* __restrict__ out)
{
    __shared__ __align__(16) char vsm[128 * 144];   // V fp16 [128px][72 halves]

    int tid  = threadIdx.x;
    int warp = tid >> 5, lane = tid & 31;
    int g = lane >> 2, tig = lane & 3;
    int n = blockIdx.y;
    int blockbase = blockIdx.x * 128;

    int ps = min(blockbase + tid, HWO - 1);
    int ys = ps / WO, xs = ps % WO;

    const uint4* xh  = g_xh + (size_t)n * 16 * HW;
    const float* off = g_offset + (size_t)n * C2 * HWO + ps;

    float acc[3][4][4];
#pragma unroll
    for (int mt = 0; mt < 3; mt++)
#pragma unroll
        for (int nt = 0; nt < 4; nt++)
#pragma unroll
            for (int i = 0; i < 4; i++) acc[mt][nt][i] = 0.f;

    char* myrow = vsm + (size_t)tid * 144;

    for (int s = 0; s < 18; s++) {
        int t = s >> 1, dg = s & 1;
        int ti = t / 3, tj = t % 3;

        float dy = off[(dg * 18 + t * 2    ) * HWO];
        float dx = off[(dg * 18 + t * 2 + 1) * HWO];
        Ctx C = make_ctx(ys, xs, ti, tj, dy, dx);
        ull W00p = pack2(C.W00, C.W00), W01p = pack2(C.W01, C.W01);
        ull W10p = pack2(C.W10, C.W10), W11p = pack2(C.W11, C.W11);

#pragma unroll 4
        for (int cg = 0; cg < 8; cg++) {
            const uint4* pc = xh + (size_t)(dg * 8 + cg) * HW;
            uint4 q00 = __ldg(pc + C.o00);
            uint4 q01 = __ldg(pc + C.o01);
            uint4 q10 = __ldg(pc + C.o10);
            uint4 q11 = __ldg(pc + C.o11);
            const unsigned* u00 = (const unsigned*)&q00;
            const unsigned* u01 = (const unsigned*)&q01;
            const unsigned* u10 = (const unsigned*)&q10;
            const unsigned* u11 = (const unsigned*)&q11;
            uint4 hv;
            unsigned* hp = (unsigned*)&hv;
#pragma unroll
            for (int i = 0; i < 4; i++) {
                float2 f00 = __half22float2(*(const __half2*)&u00[i]);
                float2 f01 = __half22float2(*(const __half2*)&u01[i]);
                float2 f10 = __half22float2(*(const __half2*)&u10[i]);
                float2 f11 = __half22float2(*(const __half2*)&u11[i]);
                ull v = fma2(W00p, pack2(f00.x, f00.y),
                        fma2(W01p, pack2(f01.x, f01.y),
                        fma2(W10p, pack2(f10.x, f10.y),
                        mul2(W11p, pack2(f11.x, f11.y)))));
                hp[i] = h2pack(lo2(v), hi2(v));
            }
            *(uint4*)(myrow + cg * 16) = hv;
        }
        __syncwarp();

        uint4 af[12];
#pragma unroll
        for (int f = 0; f < 12; f++)
            af[f] = __ldg(&g_wfrag[(s * 12 + f) * 32 + lane]);

#pragma unroll
        for (int nt = 0; nt < 4; nt++) {
            const char* rb = vsm + (size_t)(warp * 32 + nt * 8 + g) * 144
                           + tig * 4;
            unsigned b[8];
#pragma unroll
            for (int kt = 0; kt < 4; kt++) {
                b[2 * kt]     = *(const unsigned*)(rb + kt * 32);
                b[2 * kt + 1] = *(const unsigned*)(rb + kt * 32 + 16);
            }
#pragma unroll
            for (int mt = 0; mt < 3; mt++)
#pragma unroll
                for (int kt = 0; kt < 4; kt++)
                    mma16816(acc[mt][nt], af[mt * 4 + kt],
                             b[2 * kt], b[2 * kt + 1]);
        }
        __syncwarp();
    }

    // ---- epilogue: bias + Mish, float2 stores
    // p even & HWO even => p < HWO implies p+1 < HWO.
    float* ob = out + (size_t)n * C2 * HWO;
#pragma unroll
    for (int mt = 0; mt < 3; mt++) {
        int o0 = mt * 16 + g;
        int o1 = o0 + 8;
#pragma unroll
        for (int nt = 0; nt < 4; nt++) {
            int p = blockbase + warp * 32 + nt * 8 + 2 * tig;
            if (p >= HWO) continue;
            const float* a = acc[mt][nt];
#pragma unroll
            for (int h = 0; h < 2; h++) {
                int o = h ? o1 : o0;
                if (o < C2) {
                    float b = __ldg(g_bias + o);
                    float z0 = a[h * 2 + 0] + b;
                    float z1 = a[h * 2 + 1] + b;
                    float sp0 = (z0 > 20.f) ? z0 : log1pf(expf(z0));
                    float sp1 = (z1 > 20.f) ? z1 : log1pf(expf(z1));
                    *(float2*)(ob + (size_t)o * HWO + p) =
                        make_float2(z0 * tanhf(sp0), z1 * tanhf(sp1));
                }
            }
        }
    }
}

// ---------------------------------------------------------------------------
extern "C" void kernel_launch(void* const* d_in, const int* in_sizes, int n_in,
                              void* d_out, int out_size)
{
    const float* x        = (const float*)d_in[0];
    const float* conv_w   = (const float*)d_in[1];
    const float* deform_w = (const float*)d_in[2];
    const float* bn_gamma = (const float*)d_in[3];
    const float* bn_beta  = (const float*)d_in[4];
    const float* bn_mean  = (const float*)d_in[5];
    const float* bn_var   = (const float*)d_in[6];
    float* out = (float*)d_out;

    pack_kernel<<<dim3(HW / 256, 16, NN), 256>>>(
        x, deform_w, conv_w, bn_gamma, bn_beta, bn_mean, bn_var);

    offset_mma_kernel<<<dim3((HWO + 127) / 128, NN * 4), 128>>>();

    deform_kernel<<<dim3((HWO + 127) / 128, NN), 128>>>(out);
}